// round 14
// baseline (speedup 1.0000x reference)
#include <cuda_runtime.h>

#define NB  8
#define SEQ 2048
#define DIN 512
#define DK  64
#define MTOT (NB*SEQ)   // 16384
#define SPLIT 4         // flash split-K factor

// Scratch — __device__ globals, no allocation.
// g_qt: Q tf32 bits, pre-scaled by 0.125*log2(e), layout [MTOT][64].
// g_kp: K tf32 bits, column-pair permuted: within each 8-col group, order
//       (0,4,1,5,2,6,3,7) so B-frag words (c, c+4) are adjacent.
// g_vp: V tf32 bits, row-pair interleaved per 64-key tile:
//       tile T, local key kl -> row T*32 + (kl>>3)*4 + (kl&3), word col*2 + ((kl>>2)&1).
// g_wp: W tf32 bits, row-pair interleaved per 64-k chunk (same scheme as V).
__device__ unsigned g_qt[MTOT * DK];
__device__ unsigned g_kp[MTOT * DK];
__device__ unsigned g_vp[MTOT * DK];
__device__ unsigned g_wp[3 * DIN * DK];
__device__ float g_op[SPLIT * MTOT * DK];   // unnormalized partial O
__device__ float g_ms[SPLIT * MTOT];        // per-split row max (log2 domain)
__device__ float g_ls[SPLIT * MTOT];        // per-split row sum

#define QSCALE 0.18033688011112042f   // 0.125 * log2(e)

// ---------------------------------------------------------------------------
// Helpers
// ---------------------------------------------------------------------------
__device__ __forceinline__ unsigned f2tf(float f) {
    unsigned u;
    asm("cvt.rna.tf32.f32 %0, %1;" : "=r"(u) : "f"(f));
    return u;
}

__device__ __forceinline__ void mma8(float c[4],
                                     unsigned a0, unsigned a1, unsigned a2, unsigned a3,
                                     unsigned b0, unsigned b1) {
    asm volatile(
        "mma.sync.aligned.m16n8k8.row.col.f32.tf32.tf32.f32 "
        "{%0,%1,%2,%3}, {%4,%5,%6,%7}, {%8,%9}, {%0,%1,%2,%3};\n"
        : "+f"(c[0]), "+f"(c[1]), "+f"(c[2]), "+f"(c[3])
        : "r"(a0), "r"(a1), "r"(a2), "r"(a3), "r"(b0), "r"(b1));
}

__device__ __forceinline__ void cp16(const void* s, const void* g) {
    unsigned a = (unsigned)__cvta_generic_to_shared(s);
    asm volatile("cp.async.ca.shared.global [%0], [%1], 16;\n" :: "r"(a), "l"(g));
}
#define CP_COMMIT() asm volatile("cp.async.commit_group;\n" ::: "memory")
#define CP_WAIT1()  asm volatile("cp.async.wait_group 1;\n" ::: "memory")

// row-pair layout index inside a 64-row tile: rows 32, words 128
__device__ __forceinline__ int rp_row(int kl) { return (kl >> 3) * 4 + (kl & 3); }
__device__ __forceinline__ int rp_h(int kl)   { return (kl >> 2) & 1; }
// column-pair permutation within a row
__device__ __forceinline__ int cp_col(int c) {
    return (c & ~7) | ((c & 3) << 1) | ((c >> 2) & 1);
}

// ---------------------------------------------------------------------------
// One-time weight conversion: W[512,64] x3 -> tf32 bits, row-pair interleaved
// per 64-row chunk. Thread handles 4 logical columns of one k-row.
// ---------------------------------------------------------------------------
__global__ __launch_bounds__(256) void convert_w(
    const float* __restrict__ Wq, const float* __restrict__ Wk,
    const float* __restrict__ Wv)
{
    const int v = blockIdx.x * 256 + threadIdx.x;   // 3 * 512 * 16 = 24576
    const int which = v >> 13;
    const int rem = v & 8191;
    const int k  = rem >> 4;
    const int n0 = (rem & 15) * 4;
    const float* W = which == 0 ? Wq : which == 1 ? Wk : Wv;
    float4 w = *(const float4*)&W[(size_t)k * DK + n0];
    const int kl = k & 63;
    const size_t base = (size_t)which * DIN * DK + (k >> 6) * 4096
                      + rp_row(kl) * 128 + rp_h(kl);
    g_wp[base + (size_t)(n0 + 0) * 2] = f2tf(w.x);
    g_wp[base + (size_t)(n0 + 1) * 2] = f2tf(w.y);
    g_wp[base + (size_t)(n0 + 2) * 2] = f2tf(w.z);
    g_wp[base + (size_t)(n0 + 3) * 2] = f2tf(w.w);
}

// ---------------------------------------------------------------------------
// Fused projection, cp.async double-buffered. blockIdx.y selects (q|k|v).
// Block = 256 threads (8 warps), 128x64 output tile. 2-term split-tf32 for X.
// W B-frags are pair-packed -> one LDS.64 per MMA-pair.
// Epilogue writes tf32 bits into the attention-ready permuted layouts.
// ---------------------------------------------------------------------------
#define XSP 68    // X smem stride (floats): conflict-free A-frag pattern
#define WSPP 136  // W smem stride (uints): conflict-free LDS.64 pattern

__global__ __launch_bounds__(256) void proj_mma(
    const float* __restrict__ Xq, const float* __restrict__ Xk, const float* __restrict__ Xv,
    const float* __restrict__ bq, const float* __restrict__ bk, const float* __restrict__ bv)
{
    extern __shared__ float psm[];
    float*    Xs = psm;                              // [2][128*XSP]
    unsigned* Ws = (unsigned*)(psm + 2 * 128 * XSP); // [2][32*WSPP]

    const int which = blockIdx.y;
    const float* X    = which == 0 ? Xq : which == 1 ? Xk : Xv;
    const float* bias = which == 0 ? bq : which == 1 ? bk : bv;
    const unsigned* Wg = &g_wp[(size_t)which * DIN * DK];

    const int tid  = threadIdx.x;
    const int warp = tid >> 5;
    const int lane = tid & 31;
    const int gid  = lane >> 2;
    const int tg   = lane & 3;
    const int r0   = blockIdx.x * 128;

    auto stage = [&](int buf, int chunk) {
        float* Xb = Xs + buf * 128 * XSP;
        unsigned* Wb = Ws + buf * 32 * WSPP;
#pragma unroll
        for (int v = tid; v < 2048; v += 256) {   // X: 128x64 fp32
            int row = v >> 4, c4 = (v & 15) * 4;
            cp16(&Xb[row * XSP + c4], &X[(size_t)(r0 + row) * DIN + chunk * 64 + c4]);
        }
#pragma unroll
        for (int v = tid; v < 1024; v += 256) {   // W chunk: 32x128 u32
            int row = v >> 5, c4 = (v & 31) * 4;
            cp16(&Wb[row * WSPP + c4], &Wg[(size_t)chunk * 4096 + row * 128 + c4]);
        }
    };

    float acc[8][4];
#pragma unroll
    for (int n = 0; n < 8; n++)
#pragma unroll
        for (int j = 0; j < 4; j++) acc[n][j] = 0.0f;

    stage(0, 0);
    CP_COMMIT();

    for (int c = 0; c < 8; c++) {
        const int buf = c & 1;
        if (c < 7) stage(buf ^ 1, c + 1);
        CP_COMMIT();
        CP_WAIT1();
        __syncthreads();

        const float* Xb = Xs + buf * 128 * XSP;
        const unsigned* Wb = Ws + buf * 32 * WSPP;
#pragma unroll
        for (int ks = 0; ks < 8; ks++) {
            const int arow = warp * 16 + gid;
            const int acol = ks * 8 + tg;
            float f0 = Xb[arow * XSP + acol];
            float f1 = Xb[(arow + 8) * XSP + acol];
            float f2 = Xb[arow * XSP + acol + 4];
            float f3 = Xb[(arow + 8) * XSP + acol + 4];
            unsigned ah0 = f2tf(f0), ah1 = f2tf(f1), ah2 = f2tf(f2), ah3 = f2tf(f3);
            unsigned al0 = f2tf(f0 - __uint_as_float(ah0));
            unsigned al1 = f2tf(f1 - __uint_as_float(ah1));
            unsigned al2 = f2tf(f2 - __uint_as_float(ah2));
            unsigned al3 = f2tf(f3 - __uint_as_float(ah3));
#pragma unroll
            for (int nt = 0; nt < 8; nt++) {
                uint2 ww = *(const uint2*)&Wb[(ks * 4 + tg) * WSPP + (nt * 8 + gid) * 2];
                mma8(acc[nt], ah0, ah1, ah2, ah3, ww.x, ww.y);
                mma8(acc[nt], al0, al1, al2, al3, ww.x, ww.y);
            }
        }
        __syncthreads();
    }

    // Epilogue: add bias, convert to tf32 bits, write into permuted layouts.
    const int row = r0 + warp * 16 + gid;
    if (which == 0) {
        // Q: standard layout, pre-scaled
#pragma unroll
        for (int nt = 0; nt < 8; nt++) {
            const int col = nt * 8 + tg * 2;
            float b0 = bias[col], b1 = bias[col + 1];
            *(uint2*)&g_qt[(size_t)row * DK + col] = make_uint2(
                f2tf((acc[nt][0] + b0) * QSCALE), f2tf((acc[nt][1] + b1) * QSCALE));
            *(uint2*)&g_qt[(size_t)(row + 8) * DK + col] = make_uint2(
                f2tf((acc[nt][2] + b0) * QSCALE), f2tf((acc[nt][3] + b1) * QSCALE));
        }
    } else if (which == 1) {
        // K: column-pair permuted
#pragma unroll
        for (int nt = 0; nt < 8; nt++) {
            const int col = nt * 8 + tg * 2;
            float b0 = bias[col], b1 = bias[col + 1];
            g_kp[(size_t)row * DK + cp_col(col)]           = f2tf(acc[nt][0] + b0);
            g_kp[(size_t)row * DK + cp_col(col + 1)]       = f2tf(acc[nt][1] + b1);
            g_kp[(size_t)(row + 8) * DK + cp_col(col)]     = f2tf(acc[nt][2] + b0);
            g_kp[(size_t)(row + 8) * DK + cp_col(col + 1)] = f2tf(acc[nt][3] + b1);
        }
    } else {
        // V: row-pair interleaved per 64-key tile
        const int kl0 = row & 63;
        const int kl1 = (row + 8) & 63;
        const size_t b0a = ((size_t)(row >> 6) * 32 + rp_row(kl0)) * 128 + rp_h(kl0);
        const size_t b1a = ((size_t)((row + 8) >> 6) * 32 + rp_row(kl1)) * 128 + rp_h(kl1);
#pragma unroll
        for (int nt = 0; nt < 8; nt++) {
            const int col = nt * 8 + tg * 2;
            float c0 = bias[col], c1 = bias[col + 1];
            g_vp[b0a + (size_t)col * 2]       = f2tf(acc[nt][0] + c0);
            g_vp[b0a + (size_t)(col + 1) * 2] = f2tf(acc[nt][1] + c1);
            g_vp[b1a + (size_t)col * 2]       = f2tf(acc[nt][2] + c0);
            g_vp[b1a + (size_t)(col + 1) * 2] = f2tf(acc[nt][3] + c1);
        }
    }
}

// ---------------------------------------------------------------------------
// Flash attention, split-K x SPLIT, cp.async double-buffered, pair-packed
// operands (LDS.64 B-frags), exp2-domain softmax.
// Block = 128 threads (4 warps), 64-row Q tile, 64-key KV tiles.
// ---------------------------------------------------------------------------
#define KSTR 72    // K smem stride (uints): conflict-free LDS.64 pattern
#define VSTR 136   // V smem stride (uints): conflict-free LDS.64 pattern

__global__ __launch_bounds__(128) void attn_mma()
{
    extern __shared__ unsigned asmem[];
    unsigned* Ks = asmem;                 // [2][64*KSTR]
    unsigned* Vs = asmem + 2 * 64 * KSTR; // [2][32*VSTR]

    const int tid  = threadIdx.x;
    const int warp = tid >> 5;
    const int lane = tid & 31;
    const int gid  = lane >> 2;
    const int tg   = lane & 3;
    const int b    = blockIdx.y;
    const int qt   = blockIdx.x;
    const int sp   = blockIdx.z;
    const unsigned FULL = 0xffffffffu;

    // Q fragments: direct LDG of pre-scaled tf32 bits
    const size_t qoff = ((size_t)b * SEQ + qt * 64 + warp * 16) * DK;
    unsigned aq[8][4];
#pragma unroll
    for (int ks = 0; ks < 8; ks++) {
        const int c = ks * 8 + tg;
        aq[ks][0] = g_qt[qoff + (size_t)gid * DK + c];
        aq[ks][1] = g_qt[qoff + (size_t)(gid + 8) * DK + c];
        aq[ks][2] = g_qt[qoff + (size_t)gid * DK + c + 4];
        aq[ks][3] = g_qt[qoff + (size_t)(gid + 8) * DK + c + 4];
    }

    float o[8][4];
#pragma unroll
    for (int n = 0; n < 8; n++)
#pragma unroll
        for (int j = 0; j < 4; j++) o[n][j] = 0.0f;
    float m0 = -1e30f, m1 = -1e30f, l0 = 0.0f, l1 = 0.0f;

    const int src0 = (lane & ~3) | (tg >> 1);
    const int src2 = src0 + 2;
    const bool odd = tg & 1;
    const int kt0 = sp * (SEQ / 64 / SPLIT);

    auto stage = [&](int buf, int kt) {
        unsigned* Kb = Ks + buf * 64 * KSTR;
        unsigned* Vb = Vs + buf * 32 * VSTR;
        const size_t kb = ((size_t)b * SEQ + kt * 64) * DK;
        // V tile T = b*32 + kt lives at word base T * 4096 (32 rows x 128 words)
        const size_t vb = ((size_t)(b * 32 + kt)) * 4096;
#pragma unroll
        for (int v = tid; v < 1024; v += 128) {
            {   // K: 64 rows x 64 words
                int row = v >> 4, c4 = (v & 15) * 4;
                cp16(&Kb[row * KSTR + c4], &g_kp[kb + (size_t)row * DK + c4]);
            }
            {   // V: 32 rows x 128 words
                int row = v >> 5, c4 = (v & 31) * 4;
                cp16(&Vb[row * VSTR + c4], &g_vp[vb + (size_t)row * 128 + c4]);
            }
        }
    };

    stage(0, kt0);
    CP_COMMIT();

    for (int c = 0; c < SEQ / 64 / SPLIT; c++) {
        const int buf = c & 1;
        if (c < SEQ / 64 / SPLIT - 1) stage(buf ^ 1, kt0 + c + 1);
        CP_COMMIT();
        CP_WAIT1();
        __syncthreads();

        const unsigned* Kb = Ks + buf * 64 * KSTR;
        const unsigned* Vb = Vs + buf * 32 * VSTR;

        // S = Q @ K^T  (log2-domain scale pre-folded into Q)
        float s[8][4];
#pragma unroll
        for (int n = 0; n < 8; n++)
#pragma unroll
            for (int j = 0; j < 4; j++) s[n][j] = 0.0f;
#pragma unroll
        for (int ks = 0; ks < 8; ks++) {
#pragma unroll
            for (int nt = 0; nt < 8; nt++) {
                uint2 kk = *(const uint2*)&Kb[(nt * 8 + gid) * KSTR + ks * 8 + tg * 2];
                mma8(s[nt], aq[ks][0], aq[ks][1], aq[ks][2], aq[ks][3], kk.x, kk.y);
            }
        }

        // Online softmax in exp2 domain
        float rm0 = -1e30f, rm1 = -1e30f;
#pragma unroll
        for (int n = 0; n < 8; n++) {
            rm0 = fmaxf(rm0, fmaxf(s[n][0], s[n][1]));
            rm1 = fmaxf(rm1, fmaxf(s[n][2], s[n][3]));
        }
        rm0 = fmaxf(rm0, __shfl_xor_sync(FULL, rm0, 1));
        rm0 = fmaxf(rm0, __shfl_xor_sync(FULL, rm0, 2));
        rm1 = fmaxf(rm1, __shfl_xor_sync(FULL, rm1, 1));
        rm1 = fmaxf(rm1, __shfl_xor_sync(FULL, rm1, 2));
        const float mn0 = fmaxf(m0, rm0);
        const float mn1 = fmaxf(m1, rm1);
        float rs0 = 0.0f, rs1 = 0.0f;
#pragma unroll
        for (int n = 0; n < 8; n++) {
            s[n][0] = exp2f(s[n][0] - mn0);
            s[n][1] = exp2f(s[n][1] - mn0);
            s[n][2] = exp2f(s[n][2] - mn1);
            s[n][3] = exp2f(s[n][3] - mn1);
            rs0 += s[n][0] + s[n][1];
            rs1 += s[n][2] + s[n][3];
        }
        rs0 += __shfl_xor_sync(FULL, rs0, 1);
        rs0 += __shfl_xor_sync(FULL, rs0, 2);
        rs1 += __shfl_xor_sync(FULL, rs1, 1);
        rs1 += __shfl_xor_sync(FULL, rs1, 2);
        const float al0 = exp2f(m0 - mn0);
        const float al1 = exp2f(m1 - mn1);
        l0 = l0 * al0 + rs0;
        l1 = l1 * al1 + rs1;
        m0 = mn0;
        m1 = mn1;
#pragma unroll
        for (int n = 0; n < 8; n++) {
            o[n][0] *= al0; o[n][1] *= al0;
            o[n][2] *= al1; o[n][3] *= al1;
        }

        // O += P @ V ; C-frag -> A-frag via quad shuffles; V pair-packed
#pragma unroll
        for (int j = 0; j < 8; j++) {
            float x0 = __shfl_sync(FULL, s[j][0], src0);
            float x1 = __shfl_sync(FULL, s[j][1], src0);
            float y0 = __shfl_sync(FULL, s[j][0], src2);
            float y1 = __shfl_sync(FULL, s[j][1], src2);
            float z0 = __shfl_sync(FULL, s[j][2], src0);
            float z1 = __shfl_sync(FULL, s[j][3], src0);
            float w0 = __shfl_sync(FULL, s[j][2], src2);
            float w1 = __shfl_sync(FULL, s[j][3], src2);
            unsigned pa0 = f2tf(odd ? x1 : x0);
            unsigned pa1 = f2tf(odd ? z1 : z0);
            unsigned pa2 = f2tf(odd ? y1 : y0);
            unsigned pa3 = f2tf(odd ? w1 : w0);
#pragma unroll
            for (int nt = 0; nt < 8; nt++) {
                uint2 vv = *(const uint2*)&Vb[(j * 4 + tg) * VSTR + (nt * 8 + gid) * 2];
                mma8(o[nt], pa0, pa1, pa2, pa3, vv.x, vv.y);
            }
        }
        __syncthreads();
    }

    // Epilogue: store UNNORMALIZED partial O + per-row (m, l)
    const int rowb = b * SEQ + qt * 64 + warp * 16;
    const size_t obase = ((size_t)sp * MTOT + rowb) * DK;
#pragma unroll
    for (int nt = 0; nt < 8; nt++) {
        const int col = nt * 8 + tg * 2;
        *(float2*)&g_op[obase + (size_t)gid * DK + col] =
            make_float2(o[nt][0], o[nt][1]);
        *(float2*)&g_op[obase + (size_t)(gid + 8) * DK + col] =
            make_float2(o[nt][2], o[nt][3]);
    }
    if (tg == 0) {
        g_ms[sp * MTOT + rowb + gid]     = m0;
        g_ls[sp * MTOT + rowb + gid]     = l0;
        g_ms[sp * MTOT + rowb + gid + 8] = m1;
        g_ls[sp * MTOT + rowb + gid + 8] = l1;
    }
}

// ---------------------------------------------------------------------------
// Combine the SPLIT partials (vectorized float4, exp2 domain).
// ---------------------------------------------------------------------------
__global__ __launch_bounds__(256) void combine_kernel(float* __restrict__ out)
{
    const int v = blockIdx.x * 256 + threadIdx.x;   // float4 idx over MTOT*DK/4
    const int row = v >> 4;

    float mv[SPLIT];
    float M = -1e30f;
#pragma unroll
    for (int i = 0; i < SPLIT; i++) {
        mv[i] = g_ms[i * MTOT + row];
        M = fmaxf(M, mv[i]);
    }
    float L = 0.0f;
    float4 acc = make_float4(0.0f, 0.0f, 0.0f, 0.0f);
#pragma unroll
    for (int i = 0; i < SPLIT; i++) {
        const float w = exp2f(mv[i] - M);
        L += g_ls[i * MTOT + row] * w;
        float4 p = *(const float4*)&g_op[(size_t)i * MTOT * DK + (size_t)v * 4];
        acc.x += p.x * w; acc.y += p.y * w;
        acc.z += p.z * w; acc.w += p.w * w;
    }
    const float inv = 1.0f / L;
    *(float4*)&out[(size_t)v * 4] =
        make_float4(acc.x * inv, acc.y * inv, acc.z * inv, acc.w * inv);
}

// ---------------------------------------------------------------------------
extern "C" void kernel_launch(void* const* d_in, const int* in_sizes, int n_in,
                              void* d_out, int out_size)
{
    const float* q_in = (const float*)d_in[0];
    const float* k_in = (const float*)d_in[1];
    const float* v_in = (const float*)d_in[2];
    const float* Wq   = (const float*)d_in[3];
    const float* bq   = (const float*)d_in[4];
    const float* Wk   = (const float*)d_in[5];
    const float* bk   = (const float*)d_in[6];
    const float* Wv   = (const float*)d_in[7];
    const float* bv   = (const float*)d_in[8];
    float* out = (float*)d_out;

    const int proj_smem = (2 * 128 * XSP + 2 * 32 * WSPP) * 4;   // 104,448
    const int attn_smem = (2 * 64 * KSTR + 2 * 32 * VSTR) * 4;   // 71,680
    static int attr_set = 0;
    if (!attr_set) {
        cudaFuncSetAttribute(proj_mma,
                             cudaFuncAttributeMaxDynamicSharedMemorySize, proj_smem);
        cudaFuncSetAttribute(attn_mma,
                             cudaFuncAttributeMaxDynamicSharedMemorySize, attn_smem);
        attr_set = 1;
    }

    convert_w<<<96, 256>>>(Wq, Wk, Wv);

    dim3 pgrid(MTOT / 128, 3);
    proj_mma<<<pgrid, 256, proj_smem>>>(q_in, k_in, v_in, bq, bk, bv);

    dim3 agrid(SEQ / 64, NB, SPLIT);
    attn_mma<<<agrid, 128, attn_smem>>>();

    combine_kernel<<<MTOT * DK / 1024, 256>>>(out);
}

// round 16
// speedup vs baseline: 1.3888x; 1.3888x over previous
#include <cuda_runtime.h>

#define NB  8
#define SEQ 2048
#define DIN 512
#define DK  64
#define MTOT (NB*SEQ)   // 16384
#define SPLIT 4         // flash split-K factor

// Scratch — __device__ globals, no allocation.
// Projected Q (pre-scaled by 0.125*log2(e)), K, V stored as tf32 bit patterns.
__device__ unsigned g_qt[MTOT * DK];
__device__ unsigned g_kt[MTOT * DK];
__device__ unsigned g_vt[MTOT * DK];
__device__ unsigned g_wt[3 * DIN * DK];     // pre-converted tf32 weights
__device__ float g_op[SPLIT * MTOT * DK];   // unnormalized partial O
__device__ float g_ms[SPLIT * MTOT];        // per-split row max (log2 domain)
__device__ float g_ls[SPLIT * MTOT];        // per-split row sum

#define QSCALE 0.18033688011112042f   // 0.125 * log2(e)

// ---------------------------------------------------------------------------
// Helpers
// ---------------------------------------------------------------------------
__device__ __forceinline__ unsigned f2tf(float f) {
    unsigned u;
    asm("cvt.rna.tf32.f32 %0, %1;" : "=r"(u) : "f"(f));
    return u;
}

__device__ __forceinline__ void mma8(float c[4],
                                     unsigned a0, unsigned a1, unsigned a2, unsigned a3,
                                     unsigned b0, unsigned b1) {
    asm volatile(
        "mma.sync.aligned.m16n8k8.row.col.f32.tf32.tf32.f32 "
        "{%0,%1,%2,%3}, {%4,%5,%6,%7}, {%8,%9}, {%0,%1,%2,%3};\n"
        : "+f"(c[0]), "+f"(c[1]), "+f"(c[2]), "+f"(c[3])
        : "r"(a0), "r"(a1), "r"(a2), "r"(a3), "r"(b0), "r"(b1));
}

__device__ __forceinline__ void cp16(const void* s, const void* g) {
    unsigned a = (unsigned)__cvta_generic_to_shared(s);
    asm volatile("cp.async.ca.shared.global [%0], [%1], 16;\n" :: "r"(a), "l"(g));
}
#define CP_COMMIT() asm volatile("cp.async.commit_group;\n" ::: "memory")
#define CP_WAIT1()  asm volatile("cp.async.wait_group 1;\n" ::: "memory")

// ---------------------------------------------------------------------------
// One-time weight conversion: W[512,64] x3 -> tf32 bit patterns.
// ---------------------------------------------------------------------------
__global__ __launch_bounds__(256) void convert_w(
    const float* __restrict__ Wq, const float* __restrict__ Wk,
    const float* __restrict__ Wv)
{
    const int v = blockIdx.x * 256 + threadIdx.x;   // float4 index: 3*8192 total
    const int which = v >> 13;
    const int off = (v & 8191) * 4;
    const float* W = which == 0 ? Wq : which == 1 ? Wk : Wv;
    float4 w = *(const float4*)&W[off];
    *(uint4*)&g_wt[which * DIN * DK + off] =
        make_uint4(f2tf(w.x), f2tf(w.y), f2tf(w.z), f2tf(w.w));
}

// ---------------------------------------------------------------------------
// Fused projection, cp.async double-buffered. blockIdx.y selects (q|k|v).
// Block = 256 threads (8 warps), 128x64 output tile. 2-term split-tf32:
// X hi/lo split computed in the A-fragment build from raw fp32 smem.
// Epilogue writes tf32 bits (Q pre-scaled by QSCALE).
// ---------------------------------------------------------------------------
#define XSP 68   // X smem stride (floats), conflict-free A-frag pattern
#define WSP 72   // W smem stride (uints), conflict-free B-frag pattern

__global__ __launch_bounds__(256) void proj_mma(
    const float* __restrict__ Xq, const float* __restrict__ Xk, const float* __restrict__ Xv,
    const float* __restrict__ bq, const float* __restrict__ bk, const float* __restrict__ bv)
{
    extern __shared__ float psm[];
    float*    Xs = psm;                              // [2][128*XSP]
    unsigned* Ws = (unsigned*)(psm + 2 * 128 * XSP); // [2][64*WSP]

    const int which = blockIdx.y;
    const float* X    = which == 0 ? Xq : which == 1 ? Xk : Xv;
    const float* bias = which == 0 ? bq : which == 1 ? bk : bv;
    unsigned*    Y    = which == 0 ? g_qt : which == 1 ? g_kt : g_vt;
    const float oscale = which == 0 ? QSCALE : 1.0f;
    const unsigned* Wg = &g_wt[which * DIN * DK];

    const int tid  = threadIdx.x;
    const int warp = tid >> 5;
    const int lane = tid & 31;
    const int gid  = lane >> 2;
    const int tg   = lane & 3;
    const int r0   = blockIdx.x * 128;

    auto stage = [&](int buf, int kc) {
        float* Xb = Xs + buf * 128 * XSP;
        unsigned* Wb = Ws + buf * 64 * WSP;
#pragma unroll
        for (int v = tid; v < 2048; v += 256) {   // X: 128x64 fp32 = 2048 f4
            int row = v >> 4, c4 = (v & 15) * 4;
            cp16(&Xb[row * XSP + c4], &X[(size_t)(r0 + row) * DIN + kc + c4]);
        }
#pragma unroll
        for (int v = tid; v < 1024; v += 256) {   // W: 64x64 tf32 = 1024 u4
            int row = v >> 4, c4 = (v & 15) * 4;
            cp16(&Wb[row * WSP + c4], &Wg[(kc + row) * DK + c4]);
        }
    };

    float acc[8][4];
#pragma unroll
    for (int n = 0; n < 8; n++)
#pragma unroll
        for (int j = 0; j < 4; j++) acc[n][j] = 0.0f;

    stage(0, 0);
    CP_COMMIT();

    for (int c = 0; c < 8; c++) {
        const int buf = c & 1;
        if (c < 7) stage(buf ^ 1, (c + 1) * 64);
        CP_COMMIT();
        CP_WAIT1();
        __syncthreads();

        const float* Xb = Xs + buf * 128 * XSP;
        const unsigned* Wb = Ws + buf * 64 * WSP;
#pragma unroll
        for (int ks = 0; ks < 8; ks++) {
            const int arow = warp * 16 + gid;
            const int acol = ks * 8 + tg;
            float f0 = Xb[arow * XSP + acol];
            float f1 = Xb[(arow + 8) * XSP + acol];
            float f2 = Xb[arow * XSP + acol + 4];
            float f3 = Xb[(arow + 8) * XSP + acol + 4];
            unsigned ah0 = f2tf(f0), ah1 = f2tf(f1), ah2 = f2tf(f2), ah3 = f2tf(f3);
            unsigned al0 = f2tf(f0 - __uint_as_float(ah0));
            unsigned al1 = f2tf(f1 - __uint_as_float(ah1));
            unsigned al2 = f2tf(f2 - __uint_as_float(ah2));
            unsigned al3 = f2tf(f3 - __uint_as_float(ah3));
#pragma unroll
            for (int nt = 0; nt < 8; nt++) {
                unsigned b0 = Wb[(ks * 8 + tg) * WSP + nt * 8 + gid];
                unsigned b1 = Wb[(ks * 8 + tg + 4) * WSP + nt * 8 + gid];
                mma8(acc[nt], ah0, ah1, ah2, ah3, b0, b1);
                mma8(acc[nt], al0, al1, al2, al3, b0, b1);
            }
        }
        __syncthreads();
    }

    const int row = r0 + warp * 16 + gid;
#pragma unroll
    for (int nt = 0; nt < 8; nt++) {
        const int col = nt * 8 + tg * 2;
        float b0 = bias[col], b1 = bias[col + 1];
        *(uint2*)&Y[(size_t)row * DK + col] = make_uint2(
            f2tf((acc[nt][0] + b0) * oscale), f2tf((acc[nt][1] + b1) * oscale));
        *(uint2*)&Y[(size_t)(row + 8) * DK + col] = make_uint2(
            f2tf((acc[nt][2] + b0) * oscale), f2tf((acc[nt][3] + b1) * oscale));
    }
}

// ---------------------------------------------------------------------------
// Flash attention, split-K x SPLIT, cp.async double-buffered K/V tiles.
// All operands pre-converted tf32 bits; exp2-domain softmax.
// Block = 128 threads (4 warps), 64-row Q tile, 64-key KV tiles.
// KSTR=68: K B-frag pattern banks = gid*4+tg (+4) -> all 32 distinct.
// VSTR=72: V B-frag pattern banks = tg*8+gid (+32) -> all 32 distinct.
// ---------------------------------------------------------------------------
#define KSTR 68
#define VSTR 72

__global__ __launch_bounds__(128) void attn_mma()
{
    extern __shared__ unsigned asmem[];
    unsigned* Ks = asmem;                 // [2][64*KSTR]
    unsigned* Vs = asmem + 2 * 64 * KSTR; // [2][64*VSTR]

    const int tid  = threadIdx.x;
    const int warp = tid >> 5;
    const int lane = tid & 31;
    const int gid  = lane >> 2;
    const int tg   = lane & 3;
    const int b    = blockIdx.y;
    const int qt   = blockIdx.x;
    const int sp   = blockIdx.z;
    const unsigned FULL = 0xffffffffu;

    // Q fragments: direct LDG of pre-scaled tf32 bits
    const size_t qoff = ((size_t)b * SEQ + qt * 64 + warp * 16) * DK;
    unsigned aq[8][4];
#pragma unroll
    for (int ks = 0; ks < 8; ks++) {
        const int c = ks * 8 + tg;
        aq[ks][0] = g_qt[qoff + (size_t)gid * DK + c];
        aq[ks][1] = g_qt[qoff + (size_t)(gid + 8) * DK + c];
        aq[ks][2] = g_qt[qoff + (size_t)gid * DK + c + 4];
        aq[ks][3] = g_qt[qoff + (size_t)(gid + 8) * DK + c + 4];
    }

    float o[8][4];
#pragma unroll
    for (int n = 0; n < 8; n++)
#pragma unroll
        for (int j = 0; j < 4; j++) o[n][j] = 0.0f;
    float m0 = -1e30f, m1 = -1e30f, l0 = 0.0f, l1 = 0.0f;

    const int src0 = (lane & ~3) | (tg >> 1);
    const int src2 = src0 + 2;
    const bool odd = tg & 1;
    const int kt0 = sp * (SEQ / 64 / SPLIT);

    auto stage = [&](int buf, int kt) {
        const size_t kb = ((size_t)b * SEQ + kt * 64) * DK;
        unsigned* Kb = Ks + buf * 64 * KSTR;
        unsigned* Vb = Vs + buf * 64 * VSTR;
#pragma unroll
        for (int v = tid; v < 1024; v += 128) {   // 64x64 u32 = 1024 u4 each
            int row = v >> 4, c4 = (v & 15) * 4;
            cp16(&Kb[row * KSTR + c4], &g_kt[kb + (size_t)row * DK + c4]);
            cp16(&Vb[row * VSTR + c4], &g_vt[kb + (size_t)row * DK + c4]);
        }
    };

    stage(0, kt0);
    CP_COMMIT();

    for (int c = 0; c < SEQ / 64 / SPLIT; c++) {
        const int buf = c & 1;
        if (c < SEQ / 64 / SPLIT - 1) stage(buf ^ 1, kt0 + c + 1);
        CP_COMMIT();
        CP_WAIT1();
        __syncthreads();

        const unsigned* Kb = Ks + buf * 64 * KSTR;
        const unsigned* Vb = Vs + buf * 64 * VSTR;

        // S = Q @ K^T  (log2-domain scale pre-folded into Q)
        float s[8][4];
#pragma unroll
        for (int n = 0; n < 8; n++)
#pragma unroll
            for (int j = 0; j < 4; j++) s[n][j] = 0.0f;
#pragma unroll
        for (int ks = 0; ks < 8; ks++) {
#pragma unroll
            for (int nt = 0; nt < 8; nt++) {
                unsigned b0 = Kb[(nt * 8 + gid) * KSTR + ks * 8 + tg];
                unsigned b1 = Kb[(nt * 8 + gid) * KSTR + ks * 8 + tg + 4];
                mma8(s[nt], aq[ks][0], aq[ks][1], aq[ks][2], aq[ks][3], b0, b1);
            }
        }

        // Online softmax in exp2 domain
        float rm0 = -1e30f, rm1 = -1e30f;
#pragma unroll
        for (int n = 0; n < 8; n++) {
            rm0 = fmaxf(rm0, fmaxf(s[n][0], s[n][1]));
            rm1 = fmaxf(rm1, fmaxf(s[n][2], s[n][3]));
        }
        rm0 = fmaxf(rm0, __shfl_xor_sync(FULL, rm0, 1));
        rm0 = fmaxf(rm0, __shfl_xor_sync(FULL, rm0, 2));
        rm1 = fmaxf(rm1, __shfl_xor_sync(FULL, rm1, 1));
        rm1 = fmaxf(rm1, __shfl_xor_sync(FULL, rm1, 2));
        const float mn0 = fmaxf(m0, rm0);
        const float mn1 = fmaxf(m1, rm1);
        float rs0 = 0.0f, rs1 = 0.0f;
#pragma unroll
        for (int n = 0; n < 8; n++) {
            s[n][0] = exp2f(s[n][0] - mn0);
            s[n][1] = exp2f(s[n][1] - mn0);
            s[n][2] = exp2f(s[n][2] - mn1);
            s[n][3] = exp2f(s[n][3] - mn1);
            rs0 += s[n][0] + s[n][1];
            rs1 += s[n][2] + s[n][3];
        }
        rs0 += __shfl_xor_sync(FULL, rs0, 1);
        rs0 += __shfl_xor_sync(FULL, rs0, 2);
        rs1 += __shfl_xor_sync(FULL, rs1, 1);
        rs1 += __shfl_xor_sync(FULL, rs1, 2);
        const float al0 = exp2f(m0 - mn0);
        const float al1 = exp2f(m1 - mn1);
        l0 = l0 * al0 + rs0;
        l1 = l1 * al1 + rs1;
        m0 = mn0;
        m1 = mn1;
#pragma unroll
        for (int n = 0; n < 8; n++) {
            o[n][0] *= al0; o[n][1] *= al0;
            o[n][2] *= al1; o[n][3] *= al1;
        }

        // O += P @ V ; C-frag -> A-frag via quad shuffles
#pragma unroll
        for (int j = 0; j < 8; j++) {
            float x0 = __shfl_sync(FULL, s[j][0], src0);
            float x1 = __shfl_sync(FULL, s[j][1], src0);
            float y0 = __shfl_sync(FULL, s[j][0], src2);
            float y1 = __shfl_sync(FULL, s[j][1], src2);
            float z0 = __shfl_sync(FULL, s[j][2], src0);
            float z1 = __shfl_sync(FULL, s[j][3], src0);
            float w0 = __shfl_sync(FULL, s[j][2], src2);
            float w1 = __shfl_sync(FULL, s[j][3], src2);
            unsigned pa0 = f2tf(odd ? x1 : x0);
            unsigned pa1 = f2tf(odd ? z1 : z0);
            unsigned pa2 = f2tf(odd ? y1 : y0);
            unsigned pa3 = f2tf(odd ? w1 : w0);
#pragma unroll
            for (int nt = 0; nt < 8; nt++) {
                unsigned b0 = Vb[(j * 8 + tg) * VSTR + nt * 8 + gid];
                unsigned b1 = Vb[(j * 8 + tg + 4) * VSTR + nt * 8 + gid];
                mma8(o[nt], pa0, pa1, pa2, pa3, b0, b1);
            }
        }
        __syncthreads();
    }

    // Epilogue: store UNNORMALIZED partial O + per-row (m, l)
    const int rowb = b * SEQ + qt * 64 + warp * 16;
    const size_t obase = ((size_t)sp * MTOT + rowb) * DK;
#pragma unroll
    for (int nt = 0; nt < 8; nt++) {
        const int col = nt * 8 + tg * 2;
        *(float2*)&g_op[obase + (size_t)gid * DK + col] =
            make_float2(o[nt][0], o[nt][1]);
        *(float2*)&g_op[obase + (size_t)(gid + 8) * DK + col] =
            make_float2(o[nt][2], o[nt][3]);
    }
    if (tg == 0) {
        g_ms[sp * MTOT + rowb + gid]     = m0;
        g_ls[sp * MTOT + rowb + gid]     = l0;
        g_ms[sp * MTOT + rowb + gid + 8] = m1;
        g_ls[sp * MTOT + rowb + gid + 8] = l1;
    }
}

// ---------------------------------------------------------------------------
// Combine the SPLIT partials (vectorized float4, exp2 domain).
// ---------------------------------------------------------------------------
__global__ __launch_bounds__(256) void combine_kernel(float* __restrict__ out)
{
    const int v = blockIdx.x * 256 + threadIdx.x;   // float4 idx over MTOT*DK/4
    const int row = v >> 4;

    float mv[SPLIT];
    float M = -1e30f;
#pragma unroll
    for (int i = 0; i < SPLIT; i++) {
        mv[i] = g_ms[i * MTOT + row];
        M = fmaxf(M, mv[i]);
    }
    float L = 0.0f;
    float4 acc = make_float4(0.0f, 0.0f, 0.0f, 0.0f);
#pragma unroll
    for (int i = 0; i < SPLIT; i++) {
        const float w = exp2f(mv[i] - M);
        L += g_ls[i * MTOT + row] * w;
        float4 p = *(const float4*)&g_op[(size_t)i * MTOT * DK + (size_t)v * 4];
        acc.x += p.x * w; acc.y += p.y * w;
        acc.z += p.z * w; acc.w += p.w * w;
    }
    const float inv = 1.0f / L;
    *(float4*)&out[(size_t)v * 4] =
        make_float4(acc.x * inv, acc.y * inv, acc.z * inv, acc.w * inv);
}

// ---------------------------------------------------------------------------
extern "C" void kernel_launch(void* const* d_in, const int* in_sizes, int n_in,
                              void* d_out, int out_size)
{
    const float* q_in = (const float*)d_in[0];
    const float* k_in = (const float*)d_in[1];
    const float* v_in = (const float*)d_in[2];
    const float* Wq   = (const float*)d_in[3];
    const float* bq   = (const float*)d_in[4];
    const float* Wk   = (const float*)d_in[5];
    const float* bk   = (const float*)d_in[6];
    const float* Wv   = (const float*)d_in[7];
    const float* bv   = (const float*)d_in[8];
    float* out = (float*)d_out;

    const int proj_smem = (2 * 128 * XSP + 2 * 64 * WSP) * 4;           // 106,496
    const int attn_smem = (2 * 64 * KSTR + 2 * 64 * VSTR) * 4;          // 71,680
    static int attr_set = 0;
    if (!attr_set) {
        cudaFuncSetAttribute(proj_mma,
                             cudaFuncAttributeMaxDynamicSharedMemorySize, proj_smem);
        cudaFuncSetAttribute(attn_mma,
                             cudaFuncAttributeMaxDynamicSharedMemorySize, attn_smem);
        attr_set = 1;
    }

    convert_w<<<96, 256>>>(Wq, Wk, Wv);

    dim3 pgrid(MTOT / 128, 3);
    proj_mma<<<pgrid, 256, proj_smem>>>(q_in, k_in, v_in, bq, bk, bv);

    dim3 agrid(SEQ / 64, NB, SPLIT);
    attn_mma<<<agrid, 128, attn_smem>>>();

    combine_kernel<<<MTOT * DK / 1024, 256>>>(out);
}